// round 2
// baseline (speedup 1.0000x reference)
#include <cuda_runtime.h>
#include <cuda_bf16.h>
#include <math_constants.h>

// GAT layer:
//   wx    = X @ W                      (100000x128 @ 128x64)
//   s_src = wx @ a[:64], s_trg = wx @ a[64:]
//   logit_e = leaky(s_src[src]+s_trg[trg])
//   alpha   = scatter_softmax(logit, seg=src)
//   out[src] += alpha_e * wx[trg]
//
// NOTE: adjacency arrives as int32 (JAX x64 disabled canonicalizes int64->int32).

#define N_NODES_MAX 100000
#define N_EDGES_MAX 1000000
#define D_IN  128
#define D_OUT 64

// ---- scratch (allocation-free rule: __device__ globals) ----
__device__ float g_wx  [N_NODES_MAX * D_OUT];   // 25.6 MB
__device__ float g_ssrc[N_NODES_MAX];
__device__ float g_strg[N_NODES_MAX];
__device__ float g_max [N_NODES_MAX];
__device__ float g_den [N_NODES_MAX];
__device__ float g_elog[N_EDGES_MAX];           // logit, then exp() value

// ---------------------------------------------------------------------------
// K0: init out=0, den=0, max=-inf  (must run every launch: graph replays)
// ---------------------------------------------------------------------------
__global__ void k_init(float* __restrict__ out, int out_elems, int n_nodes) {
    int i = blockIdx.x * blockDim.x + threadIdx.x;
    if (i < out_elems) out[i] = 0.0f;
    if (i < n_nodes) {
        g_den[i] = 0.0f;
        g_max[i] = __int_as_float(0xff800000); // -inf
    }
}

// ---------------------------------------------------------------------------
// K1: wx = X @ W, fused s_src/s_trg epilogue.
// Block: 256 threads = 32 nodes x (8 threads x 8 cols).
// smem: X tile 16KB + W 32KB = 48KB.
// ---------------------------------------------------------------------------
__global__ __launch_bounds__(256) void k_gemm(
    const float* __restrict__ X, const float* __restrict__ W,
    const float* __restrict__ a, int n_nodes)
{
    __shared__ float Xs[32][D_IN];
    __shared__ float Ws[D_IN][D_OUT];

    const int tid   = threadIdx.x;
    const int node0 = blockIdx.x * 32;

    // cooperative loads (fully coalesced float4)
    {
        const float4* W4 = reinterpret_cast<const float4*>(W);
        float4* Ws4 = reinterpret_cast<float4*>(&Ws[0][0]);
        #pragma unroll
        for (int i = 0; i < 8; i++)                   // 128*64/4 = 2048 float4 / 256
            Ws4[tid + i * 256] = W4[tid + i * 256];

        const float4* X4 = reinterpret_cast<const float4*>(X + (size_t)node0 * D_IN);
        float4* Xs4 = reinterpret_cast<float4*>(&Xs[0][0]);
        #pragma unroll
        for (int i = 0; i < 4; i++)                   // 32*128/4 = 1024 float4 / 256
            Xs4[tid + i * 256] = X4[tid + i * 256];
    }
    __syncthreads();

    const int ty = tid >> 3;        // node within tile (0..31)
    const int tx = tid & 7;         // 8-col group (0..7)

    float acc[8];
    #pragma unroll
    for (int j = 0; j < 8; j++) acc[j] = 0.0f;

    const float* xr = Xs[ty];
    #pragma unroll 16
    for (int k = 0; k < D_IN; k++) {
        const float xv = xr[k];
        const float4 w0 = *reinterpret_cast<const float4*>(&Ws[k][tx * 8]);
        const float4 w1 = *reinterpret_cast<const float4*>(&Ws[k][tx * 8 + 4]);
        acc[0] = fmaf(xv, w0.x, acc[0]);
        acc[1] = fmaf(xv, w0.y, acc[1]);
        acc[2] = fmaf(xv, w0.z, acc[2]);
        acc[3] = fmaf(xv, w0.w, acc[3]);
        acc[4] = fmaf(xv, w1.x, acc[4]);
        acc[5] = fmaf(xv, w1.y, acc[5]);
        acc[6] = fmaf(xv, w1.z, acc[6]);
        acc[7] = fmaf(xv, w1.w, acc[7]);
    }

    const int node = node0 + ty;
    if (node < n_nodes) {
        float4* o = reinterpret_cast<float4*>(&g_wx[(size_t)node * D_OUT + tx * 8]);
        o[0] = make_float4(acc[0], acc[1], acc[2], acc[3]);
        o[1] = make_float4(acc[4], acc[5], acc[6], acc[7]);
    }

    // fused score epilogue: s_src = wx . a[:64], s_trg = wx . a[64:]
    float ps = 0.0f, pt = 0.0f;
    #pragma unroll
    for (int j = 0; j < 8; j++) {
        ps = fmaf(acc[j], __ldg(&a[tx * 8 + j]),         ps);
        pt = fmaf(acc[j], __ldg(&a[D_OUT + tx * 8 + j]), pt);
    }
    // reduce across the 8 lanes of this node (lanes contiguous, 8-aligned)
    #pragma unroll
    for (int off = 4; off > 0; off >>= 1) {
        ps += __shfl_down_sync(0xffffffffu, ps, off);
        pt += __shfl_down_sync(0xffffffffu, pt, off);
    }
    if (tx == 0 && node < n_nodes) {
        g_ssrc[node] = ps;
        g_strg[node] = pt;
    }
}

// ---------------------------------------------------------------------------
// K2: per-edge logit + leaky, store logit, atomic segment max over src.
// ---------------------------------------------------------------------------
__device__ __forceinline__ void atomicMaxFloat(float* addr, float v) {
    if (v >= 0.0f)
        atomicMax(reinterpret_cast<int*>(addr), __float_as_int(v));
    else
        atomicMin(reinterpret_cast<unsigned int*>(addr), __float_as_uint(v));
}

__global__ void k_logit_max(const int* __restrict__ src,
                            const int* __restrict__ trg,
                            int n_edges)
{
    int e = blockIdx.x * blockDim.x + threadIdx.x;
    if (e >= n_edges) return;
    const int s = src[e];
    const int t = trg[e];
    float l = g_ssrc[s] + g_strg[t];
    l = (l >= 0.0f) ? l : 0.2f * l;
    g_elog[e] = l;
    atomicMaxFloat(&g_max[s], l);
}

// ---------------------------------------------------------------------------
// K3: ex = exp(logit - segmax[src]); segment-sum denom.
// ---------------------------------------------------------------------------
__global__ void k_expsum(const int* __restrict__ src, int n_edges)
{
    int e = blockIdx.x * blockDim.x + threadIdx.x;
    if (e >= n_edges) return;
    const int s = src[e];
    const float ex = __expf(g_elog[e] - g_max[s]);
    g_elog[e] = ex;
    atomicAdd(&g_den[s], ex);
}

// ---------------------------------------------------------------------------
// K4: out[src] += (ex/den[src]) * wx[trg]
// 16 threads per edge, one float4 each, vectorized global reduction.
// ---------------------------------------------------------------------------
__global__ __launch_bounds__(256) void k_aggregate(
    const int* __restrict__ src, const int* __restrict__ trg,
    float* __restrict__ out, int n_edges)
{
    const int gt = blockIdx.x * blockDim.x + threadIdx.x;
    const int e  = gt >> 4;
    const int g  = gt & 15;
    if (e >= n_edges) return;

    const int s = src[e];
    const int t = trg[e];
    const float alpha = g_elog[e] / g_den[s];

    const float4 v = reinterpret_cast<const float4*>(g_wx)[(size_t)t * 16 + g];
    const float4 r = make_float4(v.x * alpha, v.y * alpha, v.z * alpha, v.w * alpha);

    float* p = out + (size_t)s * D_OUT + g * 4;
    asm volatile("red.global.add.v4.f32 [%0], {%1,%2,%3,%4};"
                 :: "l"(p), "f"(r.x), "f"(r.y), "f"(r.z), "f"(r.w)
                 : "memory");
}

// ---------------------------------------------------------------------------
extern "C" void kernel_launch(void* const* d_in, const int* in_sizes, int n_in,
                              void* d_out, int out_size)
{
    const float* X   = (const float*)d_in[0];        // [N,128]
    const float* W   = (const float*)d_in[1];        // [128,64]
    const float* a   = (const float*)d_in[2];        // [1,128]
    const int*   adj = (const int*)d_in[3];          // [2,E] int32 (JAX x64 off)

    const int n_nodes = in_sizes[0] / D_IN;
    const int n_edges = in_sizes[3] / 2;
    const int* src = adj;
    const int* trg = adj + n_edges;

    float* out = (float*)d_out;

    // K0: init (covers out and per-node state)
    {
        int elems = out_size > n_nodes ? out_size : n_nodes;
        int tpb = 256, blocks = (elems + tpb - 1) / tpb;
        k_init<<<blocks, tpb>>>(out, out_size, n_nodes);
    }
    // K1: GEMM + score epilogue
    {
        int blocks = (n_nodes + 31) / 32;
        k_gemm<<<blocks, 256>>>(X, W, a, n_nodes);
    }
    // K2: logit + segment max
    {
        int tpb = 256, blocks = (n_edges + tpb - 1) / tpb;
        k_logit_max<<<blocks, tpb>>>(src, trg, n_edges);
    }
    // K3: exp + segment sum
    {
        int tpb = 256, blocks = (n_edges + tpb - 1) / tpb;
        k_expsum<<<blocks, tpb>>>(src, n_edges);
    }
    // K4: weighted scatter aggregation
    {
        long long total = (long long)n_edges * 16;
        int tpb = 256;
        int blocks = (int)((total + tpb - 1) / tpb);
        k_aggregate<<<blocks, tpb>>>(src, trg, out, n_edges);
    }
}

// round 3
// speedup vs baseline: 2.5114x; 2.5114x over previous
#include <cuda_runtime.h>
#include <cuda_bf16.h>

// GAT layer, restructured:
//  K1: wx = X@W (FMA-bound blocking) + fused s_src/s_trg scores
//  K2: histogram of edge src
//  K3a/b/c: exclusive scan of counts -> row offsets
//  K4: scatter trg[e] into src-sorted order (counting sort)
//  K5: one warp per node: softmax denom (constant-shift exp, exact cancel)
//      + weighted aggregation, registers only, one store per out row.
// Adjacency arrives as int32 (JAX x64 off).

#define D_IN  128
#define D_OUT 64
#define N_NODES_MAX 100000
#define N_EDGES_MAX 1000000
#define NSCAN_PAD   100352          // 98 * 1024 >= N_NODES_MAX+1
#define SHIFT_C 8.0f

// ---- scratch (__device__ globals; allocation-free rule) ----
__device__ float g_wx   [N_NODES_MAX * D_OUT];   // 25.6 MB
__device__ float g_ssrc [N_NODES_MAX];
__device__ float g_strg [N_NODES_MAX];
__device__ int   g_cnt  [NSCAN_PAD];
__device__ int   g_rowst[NSCAN_PAD];             // row starts (exclusive scan)
__device__ int   g_curs [NSCAN_PAD];             // scatter cursors
__device__ int   g_blksum[128];
__device__ int   g_blkoff[128];
__device__ int   g_perm [N_EDGES_MAX];           // holds TRG node id, src-sorted
__device__ float g_ex   [N_EDGES_MAX];           // fallback ex stash (deg>32)

// ---------------------------------------------------------------------------
// K0: zero histogram (graph replays -> must reset every call)
// ---------------------------------------------------------------------------
__global__ void k_init(int nscan) {
    int i = blockIdx.x * blockDim.x + threadIdx.x;
    if (i < nscan) g_cnt[i] = 0;
}

// ---------------------------------------------------------------------------
// K1: GEMM. Tile: 128 nodes x 64 cols x K=128.
// 256 threads: c = tid>>5 (col group of 8), lane covers 4 nodes (lane+32i).
// W reads are warp-uniform broadcasts; X from transposed padded tile.
// Dynamic smem: Xs[128*129] + Ws[128*64] + sS[128] + sT[128] = 99840 B.
// ---------------------------------------------------------------------------
__global__ __launch_bounds__(256) void k_gemm(
    const float* __restrict__ X, const float* __restrict__ W,
    const float* __restrict__ a, int n_nodes)
{
    extern __shared__ float smem[];
    float* Xs = smem;                    // 16512 floats: [k][node], pad 129
    float* Ws = smem + 16512;            // 8192 floats:  [k][col]
    float* sS = Ws + 8192;               // 128
    float* sT = sS + 128;                // 128

    const int tid   = threadIdx.x;
    const int lane  = tid & 31;
    const int c     = tid >> 5;          // col group 0..7
    const int node0 = blockIdx.x * 128;

    if (tid < 128) { sS[tid] = 0.0f; sT[tid] = 0.0f; }

    // load W [128][64] -> Ws
    {
        const float4* W4  = reinterpret_cast<const float4*>(W);
        float4*       Ws4 = reinterpret_cast<float4*>(Ws);
        #pragma unroll
        for (int i = 0; i < 8; i++) Ws4[tid + i * 256] = W4[tid + i * 256];
    }
    // load X tile transposed: Xs[k*129 + m] = X[node0+m][k]
    {
        const float4* X4 = reinterpret_cast<const float4*>(X);
        #pragma unroll
        for (int it = 0; it < 16; it++) {
            int idx = tid + it * 256;            // 4096 float4
            int row = idx >> 5;                  // local node 0..127
            int kq  = idx & 31;                  // float4 index along k
            float4 v = make_float4(0.f, 0.f, 0.f, 0.f);
            if (node0 + row < n_nodes) v = X4[(size_t)(node0 + row) * 32 + kq];
            int k0 = kq * 4;
            Xs[(k0 + 0) * 129 + row] = v.x;
            Xs[(k0 + 1) * 129 + row] = v.y;
            Xs[(k0 + 2) * 129 + row] = v.z;
            Xs[(k0 + 3) * 129 + row] = v.w;
        }
    }
    __syncthreads();

    float acc[4][8];
    #pragma unroll
    for (int i = 0; i < 4; i++)
        #pragma unroll
        for (int j = 0; j < 8; j++) acc[i][j] = 0.0f;

    const float4* Ws4 = reinterpret_cast<const float4*>(Ws);
    #pragma unroll 8
    for (int k = 0; k < D_IN; k++) {
        const float4 w0 = Ws4[k * 16 + c * 2];       // broadcast
        const float4 w1 = Ws4[k * 16 + c * 2 + 1];
        float xv[4];
        #pragma unroll
        for (int i = 0; i < 4; i++) xv[i] = Xs[k * 129 + lane + 32 * i];
        #pragma unroll
        for (int i = 0; i < 4; i++) {
            acc[i][0] = fmaf(xv[i], w0.x, acc[i][0]);
            acc[i][1] = fmaf(xv[i], w0.y, acc[i][1]);
            acc[i][2] = fmaf(xv[i], w0.z, acc[i][2]);
            acc[i][3] = fmaf(xv[i], w0.w, acc[i][3]);
            acc[i][4] = fmaf(xv[i], w1.x, acc[i][4]);
            acc[i][5] = fmaf(xv[i], w1.y, acc[i][5]);
            acc[i][6] = fmaf(xv[i], w1.z, acc[i][6]);
            acc[i][7] = fmaf(xv[i], w1.w, acc[i][7]);
        }
    }

    // fused score partials -> smem atomics (8 contributors per node)
    {
        float av[8], bv[8];
        #pragma unroll
        for (int j = 0; j < 8; j++) {
            av[j] = __ldg(&a[c * 8 + j]);
            bv[j] = __ldg(&a[D_OUT + c * 8 + j]);
        }
        #pragma unroll
        for (int i = 0; i < 4; i++) {
            float ps = 0.f, pt = 0.f;
            #pragma unroll
            for (int j = 0; j < 8; j++) {
                ps = fmaf(acc[i][j], av[j], ps);
                pt = fmaf(acc[i][j], bv[j], pt);
            }
            atomicAdd(&sS[lane + 32 * i], ps);
            atomicAdd(&sT[lane + 32 * i], pt);
        }
    }
    __syncthreads();   // compute + score atomics done; Xs free for reuse

    // restage acc into Xs2[node][col] (pad 68, float4-aligned) for coalesced STG
    float* Xs2 = Xs;
    #pragma unroll
    for (int i = 0; i < 4; i++) {
        float4* p = reinterpret_cast<float4*>(&Xs2[(lane + 32 * i) * 68 + c * 8]);
        p[0] = make_float4(acc[i][0], acc[i][1], acc[i][2], acc[i][3]);
        p[1] = make_float4(acc[i][4], acc[i][5], acc[i][6], acc[i][7]);
    }
    __syncthreads();

    // coalesced wx store + scores
    {
        float4* wx4 = reinterpret_cast<float4*>(g_wx);
        #pragma unroll
        for (int it = 0; it < 8; it++) {
            int idx  = tid + it * 256;       // 2048 float4
            int node = idx >> 4;
            int cq   = idx & 15;
            if (node0 + node < n_nodes) {
                float4 v = *reinterpret_cast<const float4*>(&Xs2[node * 68 + cq * 4]);
                wx4[(size_t)(node0 + node) * 16 + cq] = v;
            }
        }
        if (tid < 128 && node0 + tid < n_nodes) {
            g_ssrc[node0 + tid] = sS[tid];
            g_strg[node0 + tid] = sT[tid];
        }
    }
}

// ---------------------------------------------------------------------------
// K2: histogram of src
// ---------------------------------------------------------------------------
__global__ void k_hist(const int* __restrict__ src, int n_edges) {
    int e = blockIdx.x * blockDim.x + threadIdx.x;
    if (e < n_edges) atomicAdd(&g_cnt[src[e]], 1);
}

// ---------------------------------------------------------------------------
// K3: scan (3 kernels). scanA: per-1024-block exclusive scan + block sums.
// ---------------------------------------------------------------------------
__device__ __forceinline__ int warp_incl_scan(int v, int lane) {
    #pragma unroll
    for (int o = 1; o < 32; o <<= 1) {
        int t = __shfl_up_sync(0xffffffffu, v, o);
        if (lane >= o) v += t;
    }
    return v;
}

__global__ __launch_bounds__(1024) void k_scanA(int n) {
    __shared__ int ws[32];
    const int tid  = threadIdx.x;
    const int lane = tid & 31;
    const int wid  = tid >> 5;
    const int i    = blockIdx.x * 1024 + tid;
    int v = (i < n) ? g_cnt[i] : 0;
    int s = warp_incl_scan(v, lane);
    if (lane == 31) ws[wid] = s;
    __syncthreads();
    if (wid == 0) {
        int b  = ws[lane];
        int sb = warp_incl_scan(b, lane);
        ws[lane] = sb - b;     // exclusive warp offsets
    }
    __syncthreads();
    int excl = s - v + ws[wid];
    if (i < n) g_rowst[i] = excl;
    if (tid == 1023) g_blksum[blockIdx.x] = excl + v;
}

__global__ __launch_bounds__(128) void k_scanB(int nblk) {
    __shared__ int ws[4];
    const int tid  = threadIdx.x;
    const int lane = tid & 31;
    const int wid  = tid >> 5;
    int v = (tid < nblk) ? g_blksum[tid] : 0;
    int s = warp_incl_scan(v, lane);
    if (lane == 31) ws[wid] = s;
    __syncthreads();
    int off = 0;
    #pragma unroll
    for (int w = 0; w < 4; w++) if (w < wid) off += ws[w];
    if (tid < nblk) g_blkoff[tid] = s - v + off;
}

__global__ void k_scanC(int n, int n_nodes) {
    int i = blockIdx.x * blockDim.x + threadIdx.x;
    if (i < n) {
        int r = g_rowst[i] + g_blkoff[i >> 10];
        g_rowst[i] = r;
        if (i < n_nodes) g_curs[i] = r;
    }
}

// ---------------------------------------------------------------------------
// K4: scatter. perm[pos] = TRG node (we never need the edge id itself).
// ---------------------------------------------------------------------------
__global__ void k_scatter(const int* __restrict__ src, const int* __restrict__ trg,
                          int n_edges) {
    int e = blockIdx.x * blockDim.x + threadIdx.x;
    if (e >= n_edges) return;
    int s = src[e];
    int p = atomicAdd(&g_curs[s], 1);
    g_perm[p] = trg[e];
}

// ---------------------------------------------------------------------------
// K5: one warp per node. Constant-shift exp (exact cancel in ratio),
// warp-reduced denominator, register accumulation, single out-row store.
// ---------------------------------------------------------------------------
__global__ __launch_bounds__(256) void k_aggregate(float* __restrict__ out,
                                                   int n_nodes) {
    const int warp = (blockIdx.x * blockDim.x + threadIdx.x) >> 5;
    const int lane = threadIdx.x & 31;
    if (warp >= n_nodes) return;

    const int beg = g_rowst[warp];
    const int end = g_rowst[warp + 1];
    const int deg = end - beg;
    const float ss = g_ssrc[warp];

    float den = 0.0f;
    float ex_l = 0.0f;   // this lane's ex (valid if lane < deg, deg<=32 path)
    int   t_l  = 0;

    if (deg <= 32) {
        if (lane < deg) {
            t_l = g_perm[beg + lane];
            float l = ss + g_strg[t_l];
            l = (l >= 0.0f) ? l : 0.2f * l;
            ex_l = __expf(l - SHIFT_C);
            den = ex_l;
        }
    } else {
        for (int i = beg + lane; i < end; i += 32) {
            int t = g_perm[i];
            float l = ss + g_strg[t];
            l = (l >= 0.0f) ? l : 0.2f * l;
            float ex = __expf(l - SHIFT_C);
            g_ex[i] = ex;
            den += ex;
        }
        __syncwarp();
    }
    #pragma unroll
    for (int o = 16; o > 0; o >>= 1)
        den += __shfl_xor_sync(0xffffffffu, den, o);
    const float inv = (den > 0.0f) ? (1.0f / den) : 0.0f;

    float2 acc = make_float2(0.0f, 0.0f);
    if (deg <= 32) {
        for (int j = 0; j < deg; j++) {
            float alpha = __shfl_sync(0xffffffffu, ex_l, j) * inv;
            int   t     = __shfl_sync(0xffffffffu, t_l, j);
            float2 v = *reinterpret_cast<const float2*>(&g_wx[(size_t)t * D_OUT + lane * 2]);
            acc.x = fmaf(alpha, v.x, acc.x);
            acc.y = fmaf(alpha, v.y, acc.y);
        }
    } else {
        for (int i = beg; i < end; i++) {
            float alpha = g_ex[i] * inv;     // broadcast load
            int   t     = g_perm[i];         // broadcast load
            float2 v = *reinterpret_cast<const float2*>(&g_wx[(size_t)t * D_OUT + lane * 2]);
            acc.x = fmaf(alpha, v.x, acc.x);
            acc.y = fmaf(alpha, v.y, acc.y);
        }
    }
    *reinterpret_cast<float2*>(&out[(size_t)warp * D_OUT + lane * 2]) = acc;
}

// ---------------------------------------------------------------------------
extern "C" void kernel_launch(void* const* d_in, const int* in_sizes, int n_in,
                              void* d_out, int out_size)
{
    const float* X   = (const float*)d_in[0];
    const float* W   = (const float*)d_in[1];
    const float* a   = (const float*)d_in[2];
    const int*   adj = (const int*)d_in[3];

    const int n_nodes = in_sizes[0] / D_IN;
    const int n_edges = in_sizes[3] / 2;
    const int* src = adj;
    const int* trg = adj + n_edges;
    float* out = (float*)d_out;

    const int nscan = n_nodes + 1;

    static bool attr_set = false;
    if (!attr_set) {
        cudaFuncSetAttribute(k_gemm, cudaFuncAttributeMaxDynamicSharedMemorySize,
                             (16512 + 8192 + 256) * 4);
        attr_set = true;
    }

    // K0: zero histogram
    k_init<<<(nscan + 255) / 256, 256>>>(nscan);
    // K1: GEMM + scores
    k_gemm<<<(n_nodes + 127) / 128, 256, (16512 + 8192 + 256) * 4>>>(X, W, a, n_nodes);
    // K2: histogram
    k_hist<<<(n_edges + 255) / 256, 256>>>(src, n_edges);
    // K3: scan
    int blocksA = (nscan + 1023) / 1024;
    k_scanA<<<blocksA, 1024>>>(nscan);
    k_scanB<<<1, 128>>>(blocksA);
    k_scanC<<<(nscan + 255) / 256, 256>>>(nscan, n_nodes);
    // K4: counting-sort scatter (stores trg node ids)
    k_scatter<<<(n_edges + 255) / 256, 256>>>(src, trg, n_edges);
    // K5: fused softmax + aggregation, one warp per node
    {
        long long threads = (long long)n_nodes * 32;
        k_aggregate<<<(int)((threads + 255) / 256), 256>>>(out, n_nodes);
    }
}

// round 5
// speedup vs baseline: 2.9763x; 1.1851x over previous
#include <cuda_runtime.h>
#include <cuda_bf16.h>
#include <cstdint>

// GAT layer (sm_100 baseline ISA — NO tcgen05; classic mma.sync HMMA):
//  K1: wx = X@W via bf16x3 mma.sync (hi*hi + hi*lo + lo*hi, fp32 accum)
//      + fused s_src/s_trg score epilogue
//  K2: histogram of src; K3: scan; K4: counting-sort scatter of trg
//  K5: one warp per node: constant-shift softmax + aggregation, no atomics.
// Adjacency arrives as int32 (JAX x64 off).

#define D_IN  128
#define D_OUT 64
#define N_NODES_MAX 100000
#define N_EDGES_MAX 1000000
#define NSCAN_PAD   100352
#define SHIFT_C 8.0f

// ---- scratch (__device__ globals; allocation-free rule) ----
__device__ float g_wx   [N_NODES_MAX * D_OUT];
__device__ float g_ssrc [N_NODES_MAX];
__device__ float g_strg [N_NODES_MAX];
__device__ int   g_cnt  [NSCAN_PAD];
__device__ int   g_rowst[NSCAN_PAD];
__device__ int   g_curs [NSCAN_PAD];
__device__ int   g_blksum[128];
__device__ int   g_blkoff[128];
__device__ int   g_perm [N_EDGES_MAX];
__device__ float g_ex   [N_EDGES_MAX];

// ---- helpers ----
__device__ __forceinline__ uint16_t f2bf_bits(float x) {
    uint16_t u; asm("cvt.rn.bf16.f32 %0, %1;" : "=h"(u) : "f"(x)); return u;
}
__device__ __forceinline__ float bf_bits2f(uint16_t u) {
    return __uint_as_float((uint32_t)u << 16);
}
__device__ __forceinline__ void mma_bf16(float* c, uint32_t a0, uint32_t a1,
                                         uint32_t a2, uint32_t a3,
                                         uint32_t b0, uint32_t b1) {
    asm volatile(
        "mma.sync.aligned.m16n8k16.row.col.f32.bf16.bf16.f32 "
        "{%0,%1,%2,%3}, {%4,%5,%6,%7}, {%8,%9}, {%0,%1,%2,%3};"
        : "+f"(c[0]), "+f"(c[1]), "+f"(c[2]), "+f"(c[3])
        : "r"(a0), "r"(a1), "r"(a2), "r"(a3), "r"(b0), "r"(b1));
}

// SMEM layout for the GEMM (bytes):
//   Ahi: [128 rows][k], row stride 272 (128 bf16 + 8 pad)   0      .. 34816
//   Alo:                                                    34816  .. 69632
//   Bhi: [64 n][k], stride 272                              69632  .. 87040
//   Blo:                                                    87040  .. 104448
#define A_STRIDE 272
#define OFF_ALO  34816
#define OFF_BHI  69632
#define OFF_BLO  87040
#define GEMM_SMEM_BYTES 104448

// ---------------------------------------------------------------------------
// K0: zero histogram (graph replays)
// ---------------------------------------------------------------------------
__global__ void k_init(int nscan) {
    int i = blockIdx.x * blockDim.x + threadIdx.x;
    if (i < nscan) g_cnt[i] = 0;
}

// ---------------------------------------------------------------------------
// K1: bf16x3 HMMA GEMM. CTA = 128 rows x 64 cols x K=128, 8 warps.
// ---------------------------------------------------------------------------
__global__ __launch_bounds__(256, 2) void k_gemm_mma(
    const float* __restrict__ X, const float* __restrict__ W,
    const float* __restrict__ a, int n_nodes)
{
    extern __shared__ char smem[];
    const int tid   = threadIdx.x;
    const int warp  = tid >> 5;
    const int lane  = tid & 31;
    const int r     = lane >> 2;       // 0..7
    const int c     = lane & 3;        // 0..3
    const int node0 = blockIdx.x * 128;

    // ---- load X tile -> Ahi/Alo (row-major, k-contig, stride 272B) ----
    {
        const float4* X4 = reinterpret_cast<const float4*>(X);
        #pragma unroll
        for (int it = 0; it < 16; it++) {
            int idx = tid + it * 256;          // 4096 float4
            int row = idx >> 5;                // 0..127
            int kq  = idx & 31;                // float4 idx along k
            float4 v = make_float4(0.f, 0.f, 0.f, 0.f);
            if (node0 + row < n_nodes) v = X4[(size_t)(node0 + row) * 32 + kq];
            const float xs[4] = {v.x, v.y, v.z, v.w};
            uint16_t h[4], l[4];
            #pragma unroll
            for (int j = 0; j < 4; j++) {
                h[j] = f2bf_bits(xs[j]);
                l[j] = f2bf_bits(xs[j] - bf_bits2f(h[j]));
            }
            char* p = smem + row * A_STRIDE + kq * 8;
            *reinterpret_cast<uint2*>(p) =
                make_uint2((uint32_t)h[0] | ((uint32_t)h[1] << 16),
                           (uint32_t)h[2] | ((uint32_t)h[3] << 16));
            *reinterpret_cast<uint2*>(p + OFF_ALO) =
                make_uint2((uint32_t)l[0] | ((uint32_t)l[1] << 16),
                           (uint32_t)l[2] | ((uint32_t)l[3] << 16));
        }
    }
    // ---- load W -> Bhi/Blo transposed ([n][k], stride 272B) ----
    {
        #pragma unroll
        for (int it = 0; it < 32; it++) {
            int idx = tid + it * 256;          // 8192 scalars, coalesced over n
            int k = idx >> 6, n = idx & 63;
            float w = W[idx];
            uint16_t h = f2bf_bits(w);
            uint16_t l = f2bf_bits(w - bf_bits2f(h));
            char* p = smem + OFF_BHI + n * A_STRIDE + k * 2;
            *reinterpret_cast<uint16_t*>(p) = h;
            *reinterpret_cast<uint16_t*>(p + (OFF_BLO - OFF_BHI)) = l;
        }
    }
    __syncthreads();

    // ---- main loop ----
    float acc[8][4];
    #pragma unroll
    for (int nt = 0; nt < 8; nt++)
        #pragma unroll
        for (int j = 0; j < 4; j++) acc[nt][j] = 0.0f;

    const char* pA0 = smem + (warp * 16 + r) * A_STRIDE + c * 4;   // +k0*2
    #pragma unroll
    for (int kk = 0; kk < 8; kk++) {
        const int k0b = kk * 32;               // k0*2 bytes
        uint32_t ah0 = *reinterpret_cast<const uint32_t*>(pA0 + k0b);
        uint32_t ah1 = *reinterpret_cast<const uint32_t*>(pA0 + 8 * A_STRIDE + k0b);
        uint32_t ah2 = *reinterpret_cast<const uint32_t*>(pA0 + k0b + 16);
        uint32_t ah3 = *reinterpret_cast<const uint32_t*>(pA0 + 8 * A_STRIDE + k0b + 16);
        uint32_t al0 = *reinterpret_cast<const uint32_t*>(pA0 + OFF_ALO + k0b);
        uint32_t al1 = *reinterpret_cast<const uint32_t*>(pA0 + OFF_ALO + 8 * A_STRIDE + k0b);
        uint32_t al2 = *reinterpret_cast<const uint32_t*>(pA0 + OFF_ALO + k0b + 16);
        uint32_t al3 = *reinterpret_cast<const uint32_t*>(pA0 + OFF_ALO + 8 * A_STRIDE + k0b + 16);
        #pragma unroll
        for (int nt = 0; nt < 8; nt++) {
            const char* pB = smem + OFF_BHI + (nt * 8 + r) * A_STRIDE + c * 4 + k0b;
            uint32_t bh0 = *reinterpret_cast<const uint32_t*>(pB);
            uint32_t bh1 = *reinterpret_cast<const uint32_t*>(pB + 16);
            uint32_t bl0 = *reinterpret_cast<const uint32_t*>(pB + (OFF_BLO - OFF_BHI));
            uint32_t bl1 = *reinterpret_cast<const uint32_t*>(pB + (OFF_BLO - OFF_BHI) + 16);
            mma_bf16(acc[nt], ah0, ah1, ah2, ah3, bh0, bh1);
            mma_bf16(acc[nt], ah0, ah1, ah2, ah3, bl0, bl1);
            mma_bf16(acc[nt], al0, al1, al2, al3, bh0, bh1);
        }
    }

    // ---- score epilogue ----
    // lane holds rows (warp*16+r) and (+8); cols nt*8 + 2c + {0,1}
    {
        float ps0 = 0.f, pt0 = 0.f, ps1 = 0.f, pt1 = 0.f;
        #pragma unroll
        for (int nt = 0; nt < 8; nt++) {
            #pragma unroll
            for (int j = 0; j < 2; j++) {
                int col = nt * 8 + 2 * c + j;
                float av = __ldg(&a[col]);
                float bv = __ldg(&a[64 + col]);
                ps0 = fmaf(acc[nt][j],     av, ps0);
                pt0 = fmaf(acc[nt][j],     bv, pt0);
                ps1 = fmaf(acc[nt][2 + j], av, ps1);
                pt1 = fmaf(acc[nt][2 + j], bv, pt1);
            }
        }
        #pragma unroll
        for (int o = 1; o <= 2; o <<= 1) {
            ps0 += __shfl_xor_sync(0xffffffffu, ps0, o);
            pt0 += __shfl_xor_sync(0xffffffffu, pt0, o);
            ps1 += __shfl_xor_sync(0xffffffffu, ps1, o);
            pt1 += __shfl_xor_sync(0xffffffffu, pt1, o);
        }
        if (c == 0) {
            int n0 = node0 + warp * 16 + r;
            int n1 = n0 + 8;
            if (n0 < n_nodes) { g_ssrc[n0] = ps0; g_strg[n0] = pt0; }
            if (n1 < n_nodes) { g_ssrc[n1] = ps1; g_strg[n1] = pt1; }
        }
    }

    __syncthreads();   // done reading A/B tiles; reuse smem for staging

    // ---- restage acc -> S[row][col] (pad 68 floats) for coalesced STG ----
    float* S = reinterpret_cast<float*>(smem);
    {
        const int row0 = warp * 16 + r;
        #pragma unroll
        for (int nt = 0; nt < 8; nt++) {
            *reinterpret_cast<float2*>(&S[row0 * 68 + nt * 8 + 2 * c]) =
                make_float2(acc[nt][0], acc[nt][1]);
            *reinterpret_cast<float2*>(&S[(row0 + 8) * 68 + nt * 8 + 2 * c]) =
                make_float2(acc[nt][2], acc[nt][3]);
        }
    }
    __syncthreads();
    {
        float4* wx4 = reinterpret_cast<float4*>(g_wx);
        #pragma unroll
        for (int it = 0; it < 8; it++) {
            int idx = tid + it * 256;          // 2048 float4
            int row = idx >> 4, cq = idx & 15;
            if (node0 + row < n_nodes)
                wx4[(size_t)(node0 + row) * 16 + cq] =
                    *reinterpret_cast<const float4*>(&S[row * 68 + cq * 4]);
        }
    }
}

// ---------------------------------------------------------------------------
// K2: histogram of src
// ---------------------------------------------------------------------------
__global__ void k_hist(const int* __restrict__ src, int n_edges) {
    int e = blockIdx.x * blockDim.x + threadIdx.x;
    if (e < n_edges) atomicAdd(&g_cnt[src[e]], 1);
}

// ---------------------------------------------------------------------------
// K3: scan (3 kernels)
// ---------------------------------------------------------------------------
__device__ __forceinline__ int warp_incl_scan(int v, int lane) {
    #pragma unroll
    for (int o = 1; o < 32; o <<= 1) {
        int t = __shfl_up_sync(0xffffffffu, v, o);
        if (lane >= o) v += t;
    }
    return v;
}

__global__ __launch_bounds__(1024) void k_scanA(int n) {
    __shared__ int ws[32];
    const int tid  = threadIdx.x;
    const int lane = tid & 31;
    const int wid  = tid >> 5;
    const int i    = blockIdx.x * 1024 + tid;
    int v = (i < n) ? g_cnt[i] : 0;
    int s = warp_incl_scan(v, lane);
    if (lane == 31) ws[wid] = s;
    __syncthreads();
    if (wid == 0) {
        int b  = ws[lane];
        int sb = warp_incl_scan(b, lane);
        ws[lane] = sb - b;
    }
    __syncthreads();
    int excl = s - v + ws[wid];
    if (i < n) g_rowst[i] = excl;
    if (tid == 1023) g_blksum[blockIdx.x] = excl + v;
}

__global__ __launch_bounds__(128) void k_scanB(int nblk) {
    __shared__ int ws[4];
    const int tid  = threadIdx.x;
    const int lane = tid & 31;
    const int wid  = tid >> 5;
    int v = (tid < nblk) ? g_blksum[tid] : 0;
    int s = warp_incl_scan(v, lane);
    if (lane == 31) ws[wid] = s;
    __syncthreads();
    int off = 0;
    #pragma unroll
    for (int w = 0; w < 4; w++) if (w < wid) off += ws[w];
    if (tid < nblk) g_blkoff[tid] = s - v + off;
}

__global__ void k_scanC(int n, int n_nodes) {
    int i = blockIdx.x * blockDim.x + threadIdx.x;
    if (i < n) {
        int r = g_rowst[i] + g_blkoff[i >> 10];
        g_rowst[i] = r;
        if (i < n_nodes) g_curs[i] = r;
    }
}

// ---------------------------------------------------------------------------
// K4: counting-sort scatter (stores trg node ids)
// ---------------------------------------------------------------------------
__global__ void k_scatter(const int* __restrict__ src, const int* __restrict__ trg,
                          int n_edges) {
    int e = blockIdx.x * blockDim.x + threadIdx.x;
    if (e >= n_edges) return;
    int s = src[e];
    int p = atomicAdd(&g_curs[s], 1);
    g_perm[p] = trg[e];
}

// ---------------------------------------------------------------------------
// K5: one warp per node; constant-shift exp (cancels exactly in ratio).
// ---------------------------------------------------------------------------
__global__ __launch_bounds__(256) void k_aggregate(float* __restrict__ out,
                                                   int n_nodes) {
    const int warp = (blockIdx.x * blockDim.x + threadIdx.x) >> 5;
    const int lane = threadIdx.x & 31;
    if (warp >= n_nodes) return;

    const int beg = g_rowst[warp];
    const int end = g_rowst[warp + 1];
    const int deg = end - beg;
    const float ss = g_ssrc[warp];

    float den = 0.0f;
    float ex_l = 0.0f;
    int   t_l  = 0;

    if (deg <= 32) {
        if (lane < deg) {
            t_l = g_perm[beg + lane];
            float l = ss + g_strg[t_l];
            l = (l >= 0.0f) ? l : 0.2f * l;
            ex_l = __expf(l - SHIFT_C);
            den = ex_l;
        }
    } else {
        for (int i = beg + lane; i < end; i += 32) {
            int t = g_perm[i];
            float l = ss + g_strg[t];
            l = (l >= 0.0f) ? l : 0.2f * l;
            float ex = __expf(l - SHIFT_C);
            g_ex[i] = ex;
            den += ex;
        }
        __syncwarp();
    }
    #pragma unroll
    for (int o = 16; o > 0; o >>= 1)
        den += __shfl_xor_sync(0xffffffffu, den, o);
    const float inv = (den > 0.0f) ? (1.0f / den) : 0.0f;

    float2 acc = make_float2(0.0f, 0.0f);
    if (deg <= 32) {
        for (int j = 0; j < deg; j++) {
            float alpha = __shfl_sync(0xffffffffu, ex_l, j) * inv;
            int   t     = __shfl_sync(0xffffffffu, t_l, j);
            float2 v = *reinterpret_cast<const float2*>(&g_wx[(size_t)t * D_OUT + lane * 2]);
            acc.x = fmaf(alpha, v.x, acc.x);
            acc.y = fmaf(alpha, v.y, acc.y);
        }
    } else {
        for (int i = beg; i < end; i++) {
            float alpha = g_ex[i] * inv;
            int   t     = g_perm[i];
            float2 v = *reinterpret_cast<const float2*>(&g_wx[(size_t)t * D_OUT + lane * 2]);
            acc.x = fmaf(alpha, v.x, acc.x);
            acc.y = fmaf(alpha, v.y, acc.y);
        }
    }
    *reinterpret_cast<float2*>(&out[(size_t)warp * D_OUT + lane * 2]) = acc;
}

// ---------------------------------------------------------------------------
extern "C" void kernel_launch(void* const* d_in, const int* in_sizes, int n_in,
                              void* d_out, int out_size)
{
    const float* X   = (const float*)d_in[0];
    const float* W   = (const float*)d_in[1];
    const float* a   = (const float*)d_in[2];
    const int*   adj = (const int*)d_in[3];

    const int n_nodes = in_sizes[0] / D_IN;
    const int n_edges = in_sizes[3] / 2;
    const int* src = adj;
    const int* trg = adj + n_edges;
    float* out = (float*)d_out;

    const int nscan = n_nodes + 1;

    static bool attr_set = false;
    if (!attr_set) {
        cudaFuncSetAttribute(k_gemm_mma, cudaFuncAttributeMaxDynamicSharedMemorySize,
                             GEMM_SMEM_BYTES);
        attr_set = true;
    }

    // K0: zero histogram
    k_init<<<(nscan + 255) / 256, 256>>>(nscan);
    // K1: HMMA GEMM + scores
    k_gemm_mma<<<(n_nodes + 127) / 128, 256, GEMM_SMEM_BYTES>>>(X, W, a, n_nodes);
    // K2: histogram
    k_hist<<<(n_edges + 255) / 256, 256>>>(src, n_edges);
    // K3: scan
    int blocksA = (nscan + 1023) / 1024;
    k_scanA<<<blocksA, 1024>>>(nscan);
    k_scanB<<<1, 128>>>(blocksA);
    k_scanC<<<(nscan + 255) / 256, 256>>>(nscan, n_nodes);
    // K4: counting-sort scatter
    k_scatter<<<(n_edges + 255) / 256, 256>>>(src, trg, n_edges);
    // K5: fused softmax + aggregation
    {
        long long threads = (long long)n_nodes * 32;
        k_aggregate<<<(int)((threads + 255) / 256), 256>>>(out, n_nodes);
    }
}

// round 6
// speedup vs baseline: 3.1683x; 1.0645x over previous
#include <cuda_runtime.h>
#include <cuda_bf16.h>
#include <cstdint>

// GAT layer (sm_100 baseline ISA):
//  Fork/join graph:
//   stream0: K1 GEMM (bf16x3 HMMA) + scores ----------\
//   streamB: K0 init -> K2 hist -> K3 scan -> K4 scatter } -> K5 aggregate
//  K5: one warp per node, constant-shift softmax, no atomics.
// Adjacency arrives as int32 (JAX x64 off).

#define D_IN  128
#define D_OUT 64
#define N_NODES_MAX 100000
#define N_EDGES_MAX 1000000
#define NSCAN_PAD   100352
#define SHIFT_C 8.0f

// ---- scratch (__device__ globals; allocation-free rule) ----
__device__ float g_wx   [N_NODES_MAX * D_OUT];
__device__ float g_ssrc [N_NODES_MAX];
__device__ float g_strg [N_NODES_MAX];
__device__ int   g_cnt  [NSCAN_PAD];
__device__ int   g_rowst[NSCAN_PAD];
__device__ int   g_curs [NSCAN_PAD];
__device__ int   g_blksum[128];
__device__ int   g_blkoff[128];
__device__ int   g_perm [N_EDGES_MAX];
__device__ float g_ex   [N_EDGES_MAX];

// ---- helpers ----
__device__ __forceinline__ uint16_t f2bf_bits(float x) {
    uint16_t u; asm("cvt.rn.bf16.f32 %0, %1;" : "=h"(u) : "f"(x)); return u;
}
__device__ __forceinline__ float bf_bits2f(uint16_t u) {
    return __uint_as_float((uint32_t)u << 16);
}
__device__ __forceinline__ void mma_bf16(float* c, uint32_t a0, uint32_t a1,
                                         uint32_t a2, uint32_t a3,
                                         uint32_t b0, uint32_t b1) {
    asm volatile(
        "mma.sync.aligned.m16n8k16.row.col.f32.bf16.bf16.f32 "
        "{%0,%1,%2,%3}, {%4,%5,%6,%7}, {%8,%9}, {%0,%1,%2,%3};"
        : "+f"(c[0]), "+f"(c[1]), "+f"(c[2]), "+f"(c[3])
        : "r"(a0), "r"(a1), "r"(a2), "r"(a3), "r"(b0), "r"(b1));
}

#define A_STRIDE 272
#define OFF_ALO  34816
#define OFF_BHI  69632
#define OFF_BLO  87040
#define GEMM_SMEM_BYTES 104448

// ---------------------------------------------------------------------------
// K0: zero histogram (graph replays)
// ---------------------------------------------------------------------------
__global__ void k_init(int nscan) {
    int i = blockIdx.x * blockDim.x + threadIdx.x;
    if (i < nscan) g_cnt[i] = 0;
}

// ---------------------------------------------------------------------------
// K1: bf16x3 HMMA GEMM. CTA = 128 rows x 64 cols x K=128, 8 warps.
// ---------------------------------------------------------------------------
__global__ __launch_bounds__(256, 2) void k_gemm_mma(
    const float* __restrict__ X, const float* __restrict__ W,
    const float* __restrict__ a, int n_nodes)
{
    extern __shared__ char smem[];
    const int tid   = threadIdx.x;
    const int warp  = tid >> 5;
    const int lane  = tid & 31;
    const int r     = lane >> 2;
    const int c     = lane & 3;
    const int node0 = blockIdx.x * 128;

    // ---- load X tile -> Ahi/Alo ----
    {
        const float4* X4 = reinterpret_cast<const float4*>(X);
        #pragma unroll
        for (int it = 0; it < 16; it++) {
            int idx = tid + it * 256;
            int row = idx >> 5;
            int kq  = idx & 31;
            float4 v = make_float4(0.f, 0.f, 0.f, 0.f);
            if (node0 + row < n_nodes) v = X4[(size_t)(node0 + row) * 32 + kq];
            const float xs[4] = {v.x, v.y, v.z, v.w};
            uint16_t h[4], l[4];
            #pragma unroll
            for (int j = 0; j < 4; j++) {
                h[j] = f2bf_bits(xs[j]);
                l[j] = f2bf_bits(xs[j] - bf_bits2f(h[j]));
            }
            char* p = smem + row * A_STRIDE + kq * 8;
            *reinterpret_cast<uint2*>(p) =
                make_uint2((uint32_t)h[0] | ((uint32_t)h[1] << 16),
                           (uint32_t)h[2] | ((uint32_t)h[3] << 16));
            *reinterpret_cast<uint2*>(p + OFF_ALO) =
                make_uint2((uint32_t)l[0] | ((uint32_t)l[1] << 16),
                           (uint32_t)l[2] | ((uint32_t)l[3] << 16));
        }
    }
    // ---- load W -> Bhi/Blo transposed ----
    {
        #pragma unroll
        for (int it = 0; it < 32; it++) {
            int idx = tid + it * 256;
            int k = idx >> 6, n = idx & 63;
            float w = W[idx];
            uint16_t h = f2bf_bits(w);
            uint16_t l = f2bf_bits(w - bf_bits2f(h));
            char* p = smem + OFF_BHI + n * A_STRIDE + k * 2;
            *reinterpret_cast<uint16_t*>(p) = h;
            *reinterpret_cast<uint16_t*>(p + (OFF_BLO - OFF_BHI)) = l;
        }
    }
    __syncthreads();

    float acc[8][4];
    #pragma unroll
    for (int nt = 0; nt < 8; nt++)
        #pragma unroll
        for (int j = 0; j < 4; j++) acc[nt][j] = 0.0f;

    const char* pA0 = smem + (warp * 16 + r) * A_STRIDE + c * 4;
    #pragma unroll
    for (int kk = 0; kk < 8; kk++) {
        const int k0b = kk * 32;
        uint32_t ah0 = *reinterpret_cast<const uint32_t*>(pA0 + k0b);
        uint32_t ah1 = *reinterpret_cast<const uint32_t*>(pA0 + 8 * A_STRIDE + k0b);
        uint32_t ah2 = *reinterpret_cast<const uint32_t*>(pA0 + k0b + 16);
        uint32_t ah3 = *reinterpret_cast<const uint32_t*>(pA0 + 8 * A_STRIDE + k0b + 16);
        uint32_t al0 = *reinterpret_cast<const uint32_t*>(pA0 + OFF_ALO + k0b);
        uint32_t al1 = *reinterpret_cast<const uint32_t*>(pA0 + OFF_ALO + 8 * A_STRIDE + k0b);
        uint32_t al2 = *reinterpret_cast<const uint32_t*>(pA0 + OFF_ALO + k0b + 16);
        uint32_t al3 = *reinterpret_cast<const uint32_t*>(pA0 + OFF_ALO + 8 * A_STRIDE + k0b + 16);
        #pragma unroll
        for (int nt = 0; nt < 8; nt++) {
            const char* pB = smem + OFF_BHI + (nt * 8 + r) * A_STRIDE + c * 4 + k0b;
            uint32_t bh0 = *reinterpret_cast<const uint32_t*>(pB);
            uint32_t bh1 = *reinterpret_cast<const uint32_t*>(pB + 16);
            uint32_t bl0 = *reinterpret_cast<const uint32_t*>(pB + (OFF_BLO - OFF_BHI));
            uint32_t bl1 = *reinterpret_cast<const uint32_t*>(pB + (OFF_BLO - OFF_BHI) + 16);
            mma_bf16(acc[nt], ah0, ah1, ah2, ah3, bh0, bh1);
            mma_bf16(acc[nt], ah0, ah1, ah2, ah3, bl0, bl1);
            mma_bf16(acc[nt], al0, al1, al2, al3, bh0, bh1);
        }
    }

    // ---- score epilogue ----
    {
        float ps0 = 0.f, pt0 = 0.f, ps1 = 0.f, pt1 = 0.f;
        #pragma unroll
        for (int nt = 0; nt < 8; nt++) {
            #pragma unroll
            for (int j = 0; j < 2; j++) {
                int col = nt * 8 + 2 * c + j;
                float av = __ldg(&a[col]);
                float bv = __ldg(&a[64 + col]);
                ps0 = fmaf(acc[nt][j],     av, ps0);
                pt0 = fmaf(acc[nt][j],     bv, pt0);
                ps1 = fmaf(acc[nt][2 + j], av, ps1);
                pt1 = fmaf(acc[nt][2 + j], bv, pt1);
            }
        }
        #pragma unroll
        for (int o = 1; o <= 2; o <<= 1) {
            ps0 += __shfl_xor_sync(0xffffffffu, ps0, o);
            pt0 += __shfl_xor_sync(0xffffffffu, pt0, o);
            ps1 += __shfl_xor_sync(0xffffffffu, ps1, o);
            pt1 += __shfl_xor_sync(0xffffffffu, pt1, o);
        }
        if (c == 0) {
            int n0 = node0 + warp * 16 + r;
            int n1 = n0 + 8;
            if (n0 < n_nodes) { g_ssrc[n0] = ps0; g_strg[n0] = pt0; }
            if (n1 < n_nodes) { g_ssrc[n1] = ps1; g_strg[n1] = pt1; }
        }
    }

    __syncthreads();

    // ---- restage acc -> S[row][col] (pad 68) for coalesced STG ----
    float* S = reinterpret_cast<float*>(smem);
    {
        const int row0 = warp * 16 + r;
        #pragma unroll
        for (int nt = 0; nt < 8; nt++) {
            *reinterpret_cast<float2*>(&S[row0 * 68 + nt * 8 + 2 * c]) =
                make_float2(acc[nt][0], acc[nt][1]);
            *reinterpret_cast<float2*>(&S[(row0 + 8) * 68 + nt * 8 + 2 * c]) =
                make_float2(acc[nt][2], acc[nt][3]);
        }
    }
    __syncthreads();
    {
        float4* wx4 = reinterpret_cast<float4*>(g_wx);
        #pragma unroll
        for (int it = 0; it < 8; it++) {
            int idx = tid + it * 256;
            int row = idx >> 4, cq = idx & 15;
            if (node0 + row < n_nodes)
                wx4[(size_t)(node0 + row) * 16 + cq] =
                    *reinterpret_cast<const float4*>(&S[row * 68 + cq * 4]);
        }
    }
}

// ---------------------------------------------------------------------------
// K2: histogram of src
// ---------------------------------------------------------------------------
__global__ void k_hist(const int* __restrict__ src, int n_edges) {
    int e = blockIdx.x * blockDim.x + threadIdx.x;
    if (e < n_edges) atomicAdd(&g_cnt[src[e]], 1);
}

// ---------------------------------------------------------------------------
// K3: scan (3 kernels)
// ---------------------------------------------------------------------------
__device__ __forceinline__ int warp_incl_scan(int v, int lane) {
    #pragma unroll
    for (int o = 1; o < 32; o <<= 1) {
        int t = __shfl_up_sync(0xffffffffu, v, o);
        if (lane >= o) v += t;
    }
    return v;
}

__global__ __launch_bounds__(1024) void k_scanA(int n) {
    __shared__ int ws[32];
    const int tid  = threadIdx.x;
    const int lane = tid & 31;
    const int wid  = tid >> 5;
    const int i    = blockIdx.x * 1024 + tid;
    int v = (i < n) ? g_cnt[i] : 0;
    int s = warp_incl_scan(v, lane);
    if (lane == 31) ws[wid] = s;
    __syncthreads();
    if (wid == 0) {
        int b  = ws[lane];
        int sb = warp_incl_scan(b, lane);
        ws[lane] = sb - b;
    }
    __syncthreads();
    int excl = s - v + ws[wid];
    if (i < n) g_rowst[i] = excl;
    if (tid == 1023) g_blksum[blockIdx.x] = excl + v;
}

__global__ __launch_bounds__(128) void k_scanB(int nblk) {
    __shared__ int ws[4];
    const int tid  = threadIdx.x;
    const int lane = tid & 31;
    const int wid  = tid >> 5;
    int v = (tid < nblk) ? g_blksum[tid] : 0;
    int s = warp_incl_scan(v, lane);
    if (lane == 31) ws[wid] = s;
    __syncthreads();
    int off = 0;
    #pragma unroll
    for (int w = 0; w < 4; w++) if (w < wid) off += ws[w];
    if (tid < nblk) g_blkoff[tid] = s - v + off;
}

__global__ void k_scanC(int n, int n_nodes) {
    int i = blockIdx.x * blockDim.x + threadIdx.x;
    if (i < n) {
        int r = g_rowst[i] + g_blkoff[i >> 10];
        g_rowst[i] = r;
        if (i < n_nodes) g_curs[i] = r;
    }
}

// ---------------------------------------------------------------------------
// K4: counting-sort scatter (stores trg node ids)
// ---------------------------------------------------------------------------
__global__ void k_scatter(const int* __restrict__ src, const int* __restrict__ trg,
                          int n_edges) {
    int e = blockIdx.x * blockDim.x + threadIdx.x;
    if (e >= n_edges) return;
    int s = src[e];
    int p = atomicAdd(&g_curs[s], 1);
    g_perm[p] = trg[e];
}

// ---------------------------------------------------------------------------
// K5: one warp per node; constant-shift exp (cancels exactly in ratio).
// ---------------------------------------------------------------------------
__global__ __launch_bounds__(256) void k_aggregate(float* __restrict__ out,
                                                   int n_nodes) {
    const int warp = (blockIdx.x * blockDim.x + threadIdx.x) >> 5;
    const int lane = threadIdx.x & 31;
    if (warp >= n_nodes) return;

    const int beg = g_rowst[warp];
    const int end = g_rowst[warp + 1];
    const int deg = end - beg;
    const float ss = g_ssrc[warp];

    float den = 0.0f;
    float ex_l = 0.0f;
    int   t_l  = 0;

    if (deg <= 32) {
        if (lane < deg) {
            t_l = g_perm[beg + lane];
            float l = ss + g_strg[t_l];
            l = (l >= 0.0f) ? l : 0.2f * l;
            ex_l = __expf(l - SHIFT_C);
            den = ex_l;
        }
    } else {
        for (int i = beg + lane; i < end; i += 32) {
            int t = g_perm[i];
            float l = ss + g_strg[t];
            l = (l >= 0.0f) ? l : 0.2f * l;
            float ex = __expf(l - SHIFT_C);
            g_ex[i] = ex;
            den += ex;
        }
        __syncwarp();
    }
    #pragma unroll
    for (int o = 16; o > 0; o >>= 1)
        den += __shfl_xor_sync(0xffffffffu, den, o);
    const float inv = (den > 0.0f) ? (1.0f / den) : 0.0f;

    float2 acc = make_float2(0.0f, 0.0f);
    if (deg <= 32) {
        for (int j = 0; j < deg; j++) {
            float alpha = __shfl_sync(0xffffffffu, ex_l, j) * inv;
            int   t     = __shfl_sync(0xffffffffu, t_l, j);
            float2 v = *reinterpret_cast<const float2*>(&g_wx[(size_t)t * D_OUT + lane * 2]);
            acc.x = fmaf(alpha, v.x, acc.x);
            acc.y = fmaf(alpha, v.y, acc.y);
        }
    } else {
        for (int i = beg; i < end; i++) {
            float alpha = g_ex[i] * inv;
            int   t     = g_perm[i];
            float2 v = *reinterpret_cast<const float2*>(&g_wx[(size_t)t * D_OUT + lane * 2]);
            acc.x = fmaf(alpha, v.x, acc.x);
            acc.y = fmaf(alpha, v.y, acc.y);
        }
    }
    *reinterpret_cast<float2*>(&out[(size_t)warp * D_OUT + lane * 2]) = acc;
}

// ---------------------------------------------------------------------------
extern "C" void kernel_launch(void* const* d_in, const int* in_sizes, int n_in,
                              void* d_out, int out_size)
{
    const float* X   = (const float*)d_in[0];
    const float* W   = (const float*)d_in[1];
    const float* a   = (const float*)d_in[2];
    const int*   adj = (const int*)d_in[3];

    const int n_nodes = in_sizes[0] / D_IN;
    const int n_edges = in_sizes[3] / 2;
    const int* src = adj;
    const int* trg = adj + n_edges;
    float* out = (float*)d_out;

    const int nscan = n_nodes + 1;

    // one-time host-side resources (created on first, uncaptured call)
    static cudaStream_t sB = nullptr;
    static cudaEvent_t  evFork = nullptr, evJoin = nullptr;
    if (sB == nullptr) {
        cudaFuncSetAttribute(k_gemm_mma, cudaFuncAttributeMaxDynamicSharedMemorySize,
                             GEMM_SMEM_BYTES);
        cudaStreamCreateWithFlags(&sB, cudaStreamNonBlocking);
        cudaEventCreateWithFlags(&evFork, cudaEventDisableTiming);
        cudaEventCreateWithFlags(&evJoin, cudaEventDisableTiming);
    }

    // ---- fork: edge chain on sB, GEMM on the launch stream ----
    cudaEventRecord(evFork, 0);
    cudaStreamWaitEvent(sB, evFork, 0);

    // chain B (adjacency only)
    k_init<<<(nscan + 255) / 256, 256, 0, sB>>>(nscan);
    k_hist<<<(n_edges + 255) / 256, 256, 0, sB>>>(src, n_edges);
    int blocksA = (nscan + 1023) / 1024;
    k_scanA<<<blocksA, 1024, 0, sB>>>(nscan);
    k_scanB<<<1, 128, 0, sB>>>(blocksA);
    k_scanC<<<(nscan + 255) / 256, 256, 0, sB>>>(nscan, n_nodes);
    k_scatter<<<(n_edges + 255) / 256, 256, 0, sB>>>(src, trg, n_edges);
    cudaEventRecord(evJoin, sB);

    // chain A (X, W, a only)
    k_gemm_mma<<<(n_nodes + 127) / 128, 256, GEMM_SMEM_BYTES>>>(X, W, a, n_nodes);

    // ---- join: K5 needs both chains ----
    cudaStreamWaitEvent(0, evJoin, 0);
    {
        long long threads = (long long)n_nodes * 32;
        k_aggregate<<<(int)((threads + 255) / 256), 256>>>(out, n_nodes);
    }
}